// round 7
// baseline (speedup 1.0000x reference)
#include <cuda_runtime.h>

#define NN   4096
#define IND  256
#define HID1 64
#define NH1  4
#define F1T  256
#define F2T  128

typedef unsigned long long u64;

// ---- scratch (device globals; no allocation allowed) ----
__device__ float g_Wh1[NN * F1T];
__device__ float g_h1 [NN * F1T];
__device__ float g_Wh2[NN * F2T];
__device__ float g_e1p_h[NH1 * NN], g_e1n_h[NH1 * NN];
__device__ float g_e2p_h[NH1 * NN], g_e2n_h[NH1 * NN];
__device__ float g_e1p_o[NN], g_e1n_o[NN], g_e2p_o[NN], g_e2n_o[NN];

// ---- packed fp32x2 helpers (sm_103a) ----
__device__ __forceinline__ u64 pack2(float lo, float hi) {
    return (u64)__float_as_uint(lo) | ((u64)__float_as_uint(hi) << 32);
}
__device__ __forceinline__ float lo2(u64 v) { return __uint_as_float((unsigned)v); }
__device__ __forceinline__ float hi2(u64 v) { return __uint_as_float((unsigned)(v >> 32)); }
__device__ __forceinline__ u64 fma2(u64 a, u64 b, u64 c) {
    u64 d;
    asm("fma.rn.f32x2 %0, %1, %2, %3;" : "=l"(d) : "l"(a), "l"(b), "l"(c));
    return d;
}

// ---- cp.async helpers ----
__device__ __forceinline__ unsigned sptr(const void* p) {
    return (unsigned)__cvta_generic_to_shared(p);
}
__device__ __forceinline__ void cp16(unsigned dst, const void* src) {
    asm volatile("cp.async.ca.shared.global [%0], [%1], 16;" :: "r"(dst), "l"(src) : "memory");
}
__device__ __forceinline__ void cp4(unsigned dst, const void* src) {
    asm volatile("cp.async.ca.shared.global [%0], [%1], 4;" :: "r"(dst), "l"(src) : "memory");
}
__device__ __forceinline__ void cp_commit() {
    asm volatile("cp.async.commit_group;" ::: "memory");
}
template <int N>
__device__ __forceinline__ void cp_wait() {
    asm volatile("cp.async.wait_group %0;" :: "n"(N) : "memory");
}

// =======================================================================
// GEMM: C[4096, FCOLS] = A[4096,256] @ B
// block = 32 rows x FCOLS, 512 threads, thread = 8 rows x FL feats
// per kk: 2 broadcast LDS.128 (x rows) + LDS.64/32 (B) + 4*FL FFMA2
// =======================================================================
template <int FCOLS, bool HEADS_B>
__device__ __forceinline__ void gemm_body(const float* __restrict__ A,
                                          const float* __restrict__ B,
                                          float* __restrict__ C) {
    constexpr int K = 256, XPAD = 36, FL = FCOLS / 128;
    constexpr int NCB = 32 * FCOLS / 2048;       // 16B chunks/thread for B tile
    const int tid   = threadIdx.x;
    const int feat0 = (tid & 127) * FL;
    const int r0    = (tid >> 7) * 8;
    const int row0  = blockIdx.x * 32;

    __shared__ __align__(16) float x_s[2][32 * XPAD];     // [kk][r]
    __shared__ __align__(16) float b_s[2][32 * FCOLS];    // [kk][feat]

    auto issue_tile = [&](int buf, int k0) {
#pragma unroll
        for (int i = 0; i < 2; i++) {            // x: transposed, 4B each
            int e = i * 512 + tid;
            int r = e & 31, kk = e >> 5;
            cp4(sptr(&x_s[buf][kk * XPAD + r]), &A[(row0 + r) * K + k0 + kk]);
        }
#pragma unroll
        for (int c = 0; c < NCB; c++) {          // B: flat 16B chunks
            int flat = c * 2048 + tid * 4;
            int kk = flat / FCOLS, feat = flat % FCOLS;
            const float* src = HEADS_B
                ? &B[(feat >> 6) * (IND * HID1) + (k0 + kk) * HID1 + (feat & 63)]
                : &B[(k0 + kk) * FCOLS + feat];
            cp16(sptr(&b_s[buf][flat]), src);
        }
        cp_commit();
    };

    u64 acc[4][FL];
#pragma unroll
    for (int rp = 0; rp < 4; rp++)
#pragma unroll
        for (int f = 0; f < FL; f++) acc[rp][f] = 0ull;

    issue_tile(0, 0);
    for (int t = 0; t < K / 32; t++) {
        cp_wait<0>();
        __syncthreads();
        if (t + 1 < K / 32) issue_tile((t + 1) & 1, (t + 1) * 32);
        const float* xs = x_s[t & 1];
        const float* bs = b_s[t & 1];
#pragma unroll 8
        for (int kk = 0; kk < 32; kk++) {
            ulonglong2 pv0 = *(const ulonglong2*)&xs[kk * XPAD + r0];
            ulonglong2 pv1 = *(const ulonglong2*)&xs[kk * XPAD + r0 + 4];
            if constexpr (FL == 2) {
                float2 wv = *(const float2*)&bs[kk * FCOLS + feat0];
                u64 w0 = pack2(wv.x, wv.x), w1 = pack2(wv.y, wv.y);
                acc[0][0] = fma2(pv0.x, w0, acc[0][0]);
                acc[1][0] = fma2(pv0.y, w0, acc[1][0]);
                acc[2][0] = fma2(pv1.x, w0, acc[2][0]);
                acc[3][0] = fma2(pv1.y, w0, acc[3][0]);
                acc[0][1] = fma2(pv0.x, w1, acc[0][1]);
                acc[1][1] = fma2(pv0.y, w1, acc[1][1]);
                acc[2][1] = fma2(pv1.x, w1, acc[2][1]);
                acc[3][1] = fma2(pv1.y, w1, acc[3][1]);
            } else {
                float w = bs[kk * FCOLS + feat0];
                u64 w0 = pack2(w, w);
                acc[0][0] = fma2(pv0.x, w0, acc[0][0]);
                acc[1][0] = fma2(pv0.y, w0, acc[1][0]);
                acc[2][0] = fma2(pv1.x, w0, acc[2][0]);
                acc[3][0] = fma2(pv1.y, w0, acc[3][0]);
            }
        }
        __syncthreads();
    }
#pragma unroll
    for (int i = 0; i < 8; i++) {
        u64 a0 = acc[i >> 1][0];
        float v0 = (i & 1) ? hi2(a0) : lo2(a0);
        float* cp = &C[(row0 + r0 + i) * FCOLS + feat0];
        if constexpr (FL == 2) {
            u64 a1 = acc[i >> 1][1];
            float v1 = (i & 1) ? hi2(a1) : lo2(a1);
            *(float2*)cp = make_float2(v0, v1);
        } else {
            *cp = v0;
        }
    }
}

__global__ void __launch_bounds__(512, 1) gemm1_k(const float* __restrict__ x,
                                                  const float* __restrict__ W_heads) {
    gemm_body<F1T, true>(x, W_heads, g_Wh1);
}
__global__ void __launch_bounds__(512, 1) gemm2_k(const float* __restrict__ W_out) {
    gemm_body<F2T, false>(g_h1, W_out, g_Wh2);
}

// =======================================================================
// f-vector kernels: f = Wh . a halves, then store factored-exp forms
// =======================================================================
__global__ void fvec1_k(const float* __restrict__ a_heads) {
    const int i = blockIdx.x;
    const int t = threadIdx.x;            // 0..63
    const int lane = t & 31, w = t >> 5;
    float p1[NH1], p2[NH1];
#pragma unroll
    for (int h = 0; h < NH1; h++) {
        float v = g_Wh1[i * F1T + h * HID1 + t];
        p1[h] = v * a_heads[h * (2 * HID1) + t];
        p2[h] = v * a_heads[h * (2 * HID1) + HID1 + t];
    }
#pragma unroll
    for (int off = 16; off; off >>= 1)
#pragma unroll
        for (int h = 0; h < NH1; h++) {
            p1[h] += __shfl_down_sync(0xffffffffu, p1[h], off);
            p2[h] += __shfl_down_sync(0xffffffffu, p2[h], off);
        }
    __shared__ float red[2][2 * NH1];
    if (lane == 0) {
#pragma unroll
        for (int h = 0; h < NH1; h++) { red[w][h] = p1[h]; red[w][NH1 + h] = p2[h]; }
    }
    __syncthreads();
    if (t == 0) {
#pragma unroll
        for (int h = 0; h < NH1; h++) {
            float f1 = red[0][h] + red[1][h];
            float f2 = red[0][NH1 + h] + red[1][NH1 + h];
            g_e1p_h[h * NN + i] = __expf(f1);
            g_e1n_h[h * NN + i] = __expf(0.5f * f1);
            g_e2p_h[h * NN + i] = __expf(f2);
            g_e2n_h[h * NN + i] = __expf(0.5f * f2);
        }
    }
}

__global__ void fvec2_k(const float* __restrict__ a_out) {
    const int i = blockIdx.x;
    const int t = threadIdx.x;            // 0..127
    const int lane = t & 31, w = t >> 5;
    float v  = g_Wh2[i * F2T + t];
    float p1 = v * a_out[t];
    float p2 = v * a_out[F2T + t];
#pragma unroll
    for (int off = 16; off; off >>= 1) {
        p1 += __shfl_down_sync(0xffffffffu, p1, off);
        p2 += __shfl_down_sync(0xffffffffu, p2, off);
    }
    __shared__ float red[4][2];
    if (lane == 0) { red[w][0] = p1; red[w][1] = p2; }
    __syncthreads();
    if (t == 0) {
        float f1 = red[0][0] + red[1][0] + red[2][0] + red[3][0];
        float f2 = red[0][1] + red[1][1] + red[2][1] + red[3][1];
        g_e1p_o[i] = __expf(f1);
        g_e1n_o[i] = __expf(0.5f * f1);
        g_e2p_o[i] = __expf(f2);
        g_e2n_o[i] = __expf(0.5f * f2);
    }
}

// =======================================================================
// Fused attention: block = 32 rows x F_TOT, 512 threads, 32-wide j-tiles
// Double-buffered p_s AND wh_s -> ONE __syncthreads per tile.
// accumulate thread = 8 rows x FL feats: 2 broadcast LDS.128 (p) +
//   LDS.64/32 (w) + 4*FL FFMA2  => 4 smem phases per warp-jj (minimum).
// p-phase: thread computes 4-consecutive-row p quads -> STS.128.
// p = mask * max(e1p[i]*e2p[j], e1n[i]*e2n[j])  (== mask*exp(leakyrelu))
// =======================================================================
template <int F_TOT, int NH>
__device__ __forceinline__ void attn_body(const int* __restrict__ adj,
                                          const float* __restrict__ Wh,
                                          const float* __restrict__ e1p,
                                          const float* __restrict__ e1n,
                                          const float* __restrict__ e2p,
                                          const float* __restrict__ e2n,
                                          float* __restrict__ out) {
    constexpr int TJ = 32, PPAD = 36;
    constexpr int FL = F_TOT / 128;              // 2 (L1), 1 (L2)
    constexpr int NTILES = NN / TJ;
    constexpr int NCW = TJ * F_TOT / 2048;       // 16B chunks/thread per Wh tile
    const int tid   = threadIdx.x;
    const int lane  = tid & 31, warp = tid >> 5;
    const int row0  = blockIdx.x * 32;
    const int feat0 = (tid & 127) * FL;
    const int r0    = (tid >> 7) * 8;
    const int hh    = feat0 / (F_TOT / NH);

    __shared__ __align__(16) float p_s[2][NH * TJ * PPAD];   // [h][jj][r]
    __shared__ __align__(16) float wh_s[2][TJ * F_TOT];      // [jj][feat]
    __shared__ float denom_s[32 * NH];

    auto issue_wh = [&](int buf, int j0) {
#pragma unroll
        for (int c = 0; c < NCW; c++) {
            int flat = c * 2048 + tid * 4;
            cp16(sptr(&wh_s[buf][flat]), &Wh[j0 * F_TOT + flat]);
        }
        cp_commit();
    };

    u64 acc[4][FL];
#pragma unroll
    for (int rp = 0; rp < 4; rp++)
#pragma unroll
        for (int f = 0; f < FL; f++) acc[rp][f] = 0ull;

    // ---- p-phase state ----
    constexpr int PR = (NH == 4) ? 8 : 4;        // p rows per thread
    const int  ph  = (NH == 4) ? (warp & 3) : 0;
    const int  prr = (NH == 4) ? (warp >> 2) * 8 : warp * 4;   // first p row
    const bool pact = (NH == 4) || (warp < 8);

    float E1pv[PR], E1nv[PR], dp[PR];
    float E2pv = 0.f, E2nv = 0.f;
    int   mc[PR];
#pragma unroll
    for (int i = 0; i < PR; i++) dp[i] = 0.0f;
    if (pact) {
#pragma unroll
        for (int i = 0; i < PR; i++) {
            E1pv[i] = e1p[ph * NN + row0 + prr + i];
            E1nv[i] = e1n[ph * NN + row0 + prr + i];
        }
        // prefetch tile-0 j-side factors + mask
        E2pv = e2p[ph * NN + lane];
        E2nv = e2n[ph * NN + lane];
#pragma unroll
        for (int i = 0; i < PR; i++)
            mc[i] = adj[(row0 + prr + i) * NN + lane];
    }
    issue_wh(0, 0);

    for (int t = 0; t < NTILES; t++) {
        float* ps = p_s[t & 1];
        // ---- p phase: quads of consecutive rows -> STS.128 ----
        if (pact) {
#pragma unroll
            for (int q = 0; q < PR / 4; q++) {
                float pv[4];
#pragma unroll
                for (int i = 0; i < 4; i++) {
                    float pa = E1pv[q * 4 + i] * E2pv;
                    float pb = E1nv[q * 4 + i] * E2nv;
                    float p  = (mc[q * 4 + i] > 0) ? fmaxf(pa, pb) : 0.0f;
                    dp[q * 4 + i] += p;
                    pv[i] = p;
                }
                *(float4*)&ps[(ph * TJ + lane) * PPAD + prr + q * 4] =
                    make_float4(pv[0], pv[1], pv[2], pv[3]);
            }
            // prefetch next tile's j-side regs
            if (t + 1 < NTILES) {
                const int j0n = (t + 1) * TJ;
                E2pv = e2p[ph * NN + j0n + lane];
                E2nv = e2n[ph * NN + j0n + lane];
#pragma unroll
                for (int i = 0; i < PR; i++)
                    mc[i] = adj[(row0 + prr + i) * NN + j0n + lane];
            }
        }
        cp_wait<0>();
        __syncthreads();
        if (t + 1 < NTILES) issue_wh((t + 1) & 1, (t + 1) * TJ);
        // ---- accumulate ----
        const float* ws = wh_s[t & 1];
#pragma unroll 8
        for (int jj = 0; jj < TJ; jj++) {
            ulonglong2 pv0 = *(const ulonglong2*)&ps[(hh * TJ + jj) * PPAD + r0];
            ulonglong2 pv1 = *(const ulonglong2*)&ps[(hh * TJ + jj) * PPAD + r0 + 4];
            if constexpr (FL == 2) {
                float2 wv = *(const float2*)&ws[jj * F_TOT + feat0];
                u64 w0 = pack2(wv.x, wv.x), w1 = pack2(wv.y, wv.y);
                acc[0][0] = fma2(pv0.x, w0, acc[0][0]);
                acc[1][0] = fma2(pv0.y, w0, acc[1][0]);
                acc[2][0] = fma2(pv1.x, w0, acc[2][0]);
                acc[3][0] = fma2(pv1.y, w0, acc[3][0]);
                acc[0][1] = fma2(pv0.x, w1, acc[0][1]);
                acc[1][1] = fma2(pv0.y, w1, acc[1][1]);
                acc[2][1] = fma2(pv1.x, w1, acc[2][1]);
                acc[3][1] = fma2(pv1.y, w1, acc[3][1]);
            } else {
                float w = ws[jj * F_TOT + feat0];
                u64 w0 = pack2(w, w);
                acc[0][0] = fma2(pv0.x, w0, acc[0][0]);
                acc[1][0] = fma2(pv0.y, w0, acc[1][0]);
                acc[2][0] = fma2(pv1.x, w0, acc[2][0]);
                acc[3][0] = fma2(pv1.y, w0, acc[3][0]);
            }
        }
    }

    // ---- denominator: warp-reduce over jj (= lanes) ----
    __syncthreads();
    if (pact) {
#pragma unroll
        for (int i = 0; i < PR; i++) {
            float v = dp[i];
#pragma unroll
            for (int off = 16; off; off >>= 1)
                v += __shfl_down_sync(0xffffffffu, v, off);
            if (lane == 0) denom_s[(prr + i) * NH + ph] = v;
        }
    }
    __syncthreads();

    // ---- normalize + ELU + store ----
    float inv[8];
#pragma unroll
    for (int i = 0; i < 8; i++)
        inv[i] = 1.0f / denom_s[(r0 + i) * NH + hh];
#pragma unroll
    for (int i = 0; i < 8; i++) {
        u64 a0 = acc[i >> 1][0];
        float v0 = ((i & 1) ? hi2(a0) : lo2(a0)) * inv[i];
        v0 = v0 > 0.0f ? v0 : expm1f(v0);
        float* op = &out[(row0 + r0 + i) * F_TOT + feat0];
        if constexpr (FL == 2) {
            u64 a1 = acc[i >> 1][1];
            float v1 = ((i & 1) ? hi2(a1) : lo2(a1)) * inv[i];
            v1 = v1 > 0.0f ? v1 : expm1f(v1);
            *(float2*)op = make_float2(v0, v1);
        } else {
            *op = v0;
        }
    }
}

__global__ void __launch_bounds__(512, 1) attn1_k(const int* __restrict__ adj) {
    attn_body<F1T, NH1>(adj, g_Wh1, g_e1p_h, g_e1n_h, g_e2p_h, g_e2n_h, g_h1);
}
__global__ void __launch_bounds__(512, 1) attn2_k(const int* __restrict__ adj,
                                                  float* __restrict__ out) {
    attn_body<F2T, 1>(adj, g_Wh2, g_e1p_o, g_e1n_o, g_e2p_o, g_e2n_o, out);
}

// =======================================================================
extern "C" void kernel_launch(void* const* d_in, const int* in_sizes, int n_in,
                              void* d_out, int out_size) {
    const float* x       = (const float*)d_in[0];
    const int*   adj     = (const int*)  d_in[1];
    const float* W_heads = (const float*)d_in[2];
    const float* a_heads = (const float*)d_in[3];
    const float* W_out   = (const float*)d_in[4];
    const float* a_out   = (const float*)d_in[5];
    float* out = (float*)d_out;

    gemm1_k<<<NN / 32, 512>>>(x, W_heads);
    fvec1_k<<<NN, 64>>>(a_heads);
    attn1_k<<<NN / 32, 512>>>(adj);
    gemm2_k<<<NN / 32, 512>>>(W_out);
    fvec2_k<<<NN, 128>>>(a_out);
    attn2_k<<<NN / 32, 512>>>(adj, out);
}

// round 9
// speedup vs baseline: 1.6069x; 1.6069x over previous
#include <cuda_runtime.h>

#define NN   4096
#define IND  256
#define HID1 64
#define NH1  4
#define F1T  256
#define F2T  128

typedef unsigned long long u64;

// ---- scratch (device globals; no allocation allowed) ----
__device__ float g_Wh1[NN * F1T];          // tf32-rounded
__device__ float g_h1 [NN * F1T];          // layer-1 output (fp32)
__device__ float g_Wh2[NN * F2T];          // tf32-rounded
__device__ float g_e1p_h[NH1 * NN], g_e1n_h[NH1 * NN];
__device__ float g_e2p_h[NH1 * NN], g_e2n_h[NH1 * NN];
__device__ float g_e1p_o[NN], g_e1n_o[NN], g_e2p_o[NN], g_e2n_o[NN];
__device__ unsigned g_adjbits[NN * (NN / 32)];   // 2MB packed mask

// ---- packed fp32x2 helpers (sm_103a) ----
__device__ __forceinline__ u64 pack2(float lo, float hi) {
    return (u64)__float_as_uint(lo) | ((u64)__float_as_uint(hi) << 32);
}
__device__ __forceinline__ float lo2(u64 v) { return __uint_as_float((unsigned)v); }
__device__ __forceinline__ float hi2(u64 v) { return __uint_as_float((unsigned)(v >> 32)); }
__device__ __forceinline__ u64 fma2(u64 a, u64 b, u64 c) {
    u64 d;
    asm("fma.rn.f32x2 %0, %1, %2, %3;" : "=l"(d) : "l"(a), "l"(b), "l"(c));
    return d;
}

// ---- tf32 / mma helpers ----
__device__ __forceinline__ unsigned cvt_tf32(float x) {
    unsigned u;
    asm("cvt.rna.tf32.f32 %0, %1;" : "=r"(u) : "f"(x));
    return u;
}
__device__ __forceinline__ void mma_tf32(float d[4],
        unsigned a0, unsigned a1, unsigned a2, unsigned a3,
        unsigned b0, unsigned b1) {
    asm volatile(
        "mma.sync.aligned.m16n8k8.row.col.f32.tf32.tf32.f32 "
        "{%0,%1,%2,%3}, {%4,%5,%6,%7}, {%8,%9}, {%0,%1,%2,%3};"
        : "+f"(d[0]), "+f"(d[1]), "+f"(d[2]), "+f"(d[3])
        : "r"(a0), "r"(a1), "r"(a2), "r"(a3), "r"(b0), "r"(b1));
}

// ---- cp.async helpers ----
__device__ __forceinline__ unsigned sptr(const void* p) {
    return (unsigned)__cvta_generic_to_shared(p);
}
__device__ __forceinline__ void cp16(unsigned dst, const void* src) {
    asm volatile("cp.async.ca.shared.global [%0], [%1], 16;" :: "r"(dst), "l"(src) : "memory");
}
__device__ __forceinline__ void cp4(unsigned dst, const void* src) {
    asm volatile("cp.async.ca.shared.global [%0], [%1], 4;" :: "r"(dst), "l"(src) : "memory");
}
__device__ __forceinline__ void cp_commit() {
    asm volatile("cp.async.commit_group;" ::: "memory");
}
template <int N>
__device__ __forceinline__ void cp_wait() {
    asm volatile("cp.async.wait_group %0;" :: "n"(N) : "memory");
}

// =======================================================================
// adj bit-pack: g_adjbits[row][w] bit l = adj[row][32w+l] > 0
// =======================================================================
__global__ void adjbits_k(const int* __restrict__ adj) {
    const int row  = blockIdx.x;
    const int w    = threadIdx.x >> 5;       // 4 warps
    const int lane = threadIdx.x & 31;
#pragma unroll 4
    for (int k = 0; k < 32; k++) {
        int col = w * 1024 + k * 32 + lane;
        unsigned m = __ballot_sync(0xffffffffu, adj[row * NN + col] > 0);
        if (lane == 0) g_adjbits[row * (NN / 32) + w * 32 + k] = m;
    }
}

// =======================================================================
// GEMM: C = A[4096,256] @ B, output tf32-rounded.
// block = 32 rows x FCOLS, 512 threads, thread = 4 rows x FPT feats
// =======================================================================
template <int FCOLS, bool HEADS_B>
__device__ __forceinline__ void gemm_body(const float* __restrict__ A,
                                          const float* __restrict__ B,
                                          float* __restrict__ C) {
    constexpr int K = 256, XPAD = 36, FPT = FCOLS / 64;
    constexpr int NCB = 32 * FCOLS / 2048;
    const int tid   = threadIdx.x;
    const int feat0 = (tid & 63) * FPT;
    const int r0    = (tid >> 6) * 4;
    const int row0  = blockIdx.x * 32;

    __shared__ __align__(16) float x_s[2][32 * XPAD];
    __shared__ __align__(16) float b_s[2][32 * FCOLS];

    auto issue_tile = [&](int buf, int k0) {
#pragma unroll
        for (int i = 0; i < 2; i++) {
            int e = i * 512 + tid;
            int r = e & 31, kk = e >> 5;
            cp4(sptr(&x_s[buf][kk * XPAD + r]), &A[(row0 + r) * K + k0 + kk]);
        }
#pragma unroll
        for (int c = 0; c < NCB; c++) {
            int flat = c * 2048 + tid * 4;
            int kk = flat / FCOLS, feat = flat % FCOLS;
            const float* src = HEADS_B
                ? &B[(feat >> 6) * (IND * HID1) + (k0 + kk) * HID1 + (feat & 63)]
                : &B[(k0 + kk) * FCOLS + feat];
            cp16(sptr(&b_s[buf][flat]), src);
        }
        cp_commit();
    };

    u64 acc[FPT][2];
#pragma unroll
    for (int f = 0; f < FPT; f++) { acc[f][0] = 0ull; acc[f][1] = 0ull; }

    issue_tile(0, 0);
    for (int t = 0; t < K / 32; t++) {
        if (t + 1 < K / 32) { issue_tile((t + 1) & 1, (t + 1) * 32); cp_wait<1>(); }
        else                { cp_wait<0>(); }
        __syncthreads();
        const float* xs = x_s[t & 1];
        const float* bs = b_s[t & 1];
#pragma unroll 8
        for (int kk = 0; kk < 32; kk++) {
            ulonglong2 pv = *(const ulonglong2*)&xs[kk * XPAD + r0];
            float wv[FPT];
            if constexpr (FPT == 4) {
                float4 v = *(const float4*)&bs[kk * FCOLS + feat0];
                wv[0] = v.x; wv[1] = v.y; wv[2] = v.z; wv[3] = v.w;
            } else {
                float2 v = *(const float2*)&bs[kk * FCOLS + feat0];
                wv[0] = v.x; wv[1] = v.y;
            }
#pragma unroll
            for (int f = 0; f < FPT; f++) {
                u64 w2 = pack2(wv[f], wv[f]);
                acc[f][0] = fma2(pv.x, w2, acc[f][0]);
                acc[f][1] = fma2(pv.y, w2, acc[f][1]);
            }
        }
        __syncthreads();
    }
#pragma unroll
    for (int i = 0; i < 4; i++) {
        float v[FPT];
#pragma unroll
        for (int f = 0; f < FPT; f++) {
            float raw = (i & 1) ? hi2(acc[f][i >> 1]) : lo2(acc[f][i >> 1]);
            v[f] = __uint_as_float(cvt_tf32(raw));   // tf32-round for MMA B operand
        }
        float* cp = &C[(row0 + r0 + i) * FCOLS + feat0];
        if constexpr (FPT == 4) *(float4*)cp = make_float4(v[0], v[1], v[2], v[3]);
        else                    *(float2*)cp = make_float2(v[0], v[1]);
    }
}

__global__ void __launch_bounds__(512, 1) gemm1_k(const float* __restrict__ x,
                                                  const float* __restrict__ W_heads) {
    gemm_body<F1T, true>(x, W_heads, g_Wh1);
}
__global__ void __launch_bounds__(512, 1) gemm2_k(const float* __restrict__ W_out) {
    gemm_body<F2T, false>(g_h1, W_out, g_Wh2);
}

// =======================================================================
// f-vector kernels: f = Wh . a halves, store factored-exp forms
// =======================================================================
__global__ void fvec1_k(const float* __restrict__ a_heads) {
    const int i = blockIdx.x;
    const int t = threadIdx.x;            // 0..63
    const int lane = t & 31, w = t >> 5;
    float p1[NH1], p2[NH1];
#pragma unroll
    for (int h = 0; h < NH1; h++) {
        float v = g_Wh1[i * F1T + h * HID1 + t];
        p1[h] = v * a_heads[h * (2 * HID1) + t];
        p2[h] = v * a_heads[h * (2 * HID1) + HID1 + t];
    }
#pragma unroll
    for (int off = 16; off; off >>= 1)
#pragma unroll
        for (int h = 0; h < NH1; h++) {
            p1[h] += __shfl_down_sync(0xffffffffu, p1[h], off);
            p2[h] += __shfl_down_sync(0xffffffffu, p2[h], off);
        }
    __shared__ float red[2][2 * NH1];
    if (lane == 0) {
#pragma unroll
        for (int h = 0; h < NH1; h++) { red[w][h] = p1[h]; red[w][NH1 + h] = p2[h]; }
    }
    __syncthreads();
    if (t == 0) {
#pragma unroll
        for (int h = 0; h < NH1; h++) {
            float f1 = red[0][h] + red[1][h];
            float f2 = red[0][NH1 + h] + red[1][NH1 + h];
            g_e1p_h[h * NN + i] = __expf(f1);
            g_e1n_h[h * NN + i] = __expf(0.5f * f1);
            g_e2p_h[h * NN + i] = __expf(f2);
            g_e2n_h[h * NN + i] = __expf(0.5f * f2);
        }
    }
}

__global__ void fvec2_k(const float* __restrict__ a_out) {
    const int i = blockIdx.x;
    const int t = threadIdx.x;            // 0..127
    const int lane = t & 31, w = t >> 5;
    float v  = g_Wh2[i * F2T + t];
    float p1 = v * a_out[t];
    float p2 = v * a_out[F2T + t];
#pragma unroll
    for (int off = 16; off; off >>= 1) {
        p1 += __shfl_down_sync(0xffffffffu, p1, off);
        p2 += __shfl_down_sync(0xffffffffu, p2, off);
    }
    __shared__ float red[4][2];
    if (lane == 0) { red[w][0] = p1; red[w][1] = p2; }
    __syncthreads();
    if (t == 0) {
        float f1 = red[0][0] + red[1][0] + red[2][0] + red[3][0];
        float f2 = red[0][1] + red[1][1] + red[2][1] + red[3][1];
        g_e1p_o[i] = __expf(f1);
        g_e1n_o[i] = __expf(0.5f * f1);
        g_e2p_o[i] = __expf(f2);
        g_e2n_o[i] = __expf(0.5f * f2);
    }
}

// =======================================================================
// Tensor-core attention (tf32 mma.sync, flash style)
// block = 16 rows x F feats, 512 threads, grid 256, 32-wide j-tiles.
// p tile (tf32) via SIMT -> smem (SINGLE buffer); Wh double-buffered cp.async.
// Per tile: sync -> write p + issue wh(t+1) -> wait wh(t) + sync -> mma.
// warp = m16 x (8*CHUNKS): per tile 4 ksteps x CHUNKS mma.m16n8k8.
// denominator = fp32 sum of the SAME tf32-rounded p values.
// =======================================================================
template <int F, int NH>
__device__ __forceinline__ void attn_body(const float* __restrict__ Wh,
                                          const float* __restrict__ e1p,
                                          const float* __restrict__ e1n,
                                          const float* __restrict__ e2p,
                                          const float* __restrict__ e2n,
                                          float* __restrict__ out) {
    constexpr int TJ = 32, NT = NN / TJ;
    constexpr int WS = F + 8;                    // 264 / 136 : == 8 mod 32
    constexpr int CHUNKS = F / 128;              // n8 chunks per warp (2 / 1)
    constexpr int NCW = (TJ * F / 4) / 512;      // cp16 per thread per tile
    const int tid  = threadIdx.x;
    const int lane = tid & 31, warp = tid >> 5;
    const int g = lane >> 2, c = lane & 3;
    const int row0 = blockIdx.x * 16;
    const int hw   = (warp * NH) >> 4;           // head of this mma warp

    __shared__ __align__(16) float p_s[NH * 16 * 36];        // single buffer
    __shared__ __align__(16) float wh_s[2][TJ * WS];
    __shared__ float denom_s[NH * 16];

    auto issue_wh = [&](int buf, int j0) {
#pragma unroll
        for (int cc = 0; cc < NCW; cc++) {
            int fc = cc * 512 + tid;
            int k = fc / (F / 4), off = (fc % (F / 4)) * 4;
            cp16(sptr(&wh_s[buf][k * WS + off]), &Wh[(j0 + k) * F + off]);
        }
        cp_commit();
    };

    float d[CHUNKS][4];
#pragma unroll
    for (int q = 0; q < CHUNKS; q++)
#pragma unroll
        for (int i = 0; i < 4; i++) d[q][i] = 0.0f;

    // p-compute role
    int ph, pr, pcq;
    if constexpr (NH == 4) { ph = tid >> 7; pr = (tid >> 3) & 15; pcq = (tid & 7) << 2; }
    else                   { ph = 0;        pr = tid >> 5;        pcq = tid & 31; }
    const float E1pv = e1p[ph * NN + row0 + pr];
    const float E1nv = e1n[ph * NN + row0 + pr];
    float dsum = 0.0f;

    // tile-0 prefetch (j-side factors + mask bits)
    float4 c2p4, c2n4; float c2p1, c2n1;
    if constexpr (NH == 4) {
        c2p4 = *(const float4*)&e2p[ph * NN + pcq];
        c2n4 = *(const float4*)&e2n[ph * NN + pcq];
    } else {
        c2p1 = e2p[pcq]; c2n1 = e2n[pcq];
    }
    unsigned bw = g_adjbits[(row0 + pr) * (NN / 32)];
    issue_wh(0, 0);

    for (int t = 0; t < NT; t++) {
        // sync: mma(t-1) finished reading p_s and wh[(t-1)&1]
        __syncthreads();
        // ---- p phase (write single p buffer) ----
        if constexpr (NH == 4) {
            float e2pv[4] = {c2p4.x, c2p4.y, c2p4.z, c2p4.w};
            float e2nv[4] = {c2n4.x, c2n4.y, c2n4.z, c2n4.w};
            unsigned u[4];
#pragma unroll
            for (int i = 0; i < 4; i++) {
                float pm = fmaxf(E1pv * e2pv[i], E1nv * e2nv[i]);
                float p  = ((bw >> (pcq + i)) & 1u) ? pm : 0.0f;
                u[i] = cvt_tf32(p);
                dsum += __uint_as_float(u[i]);
            }
            uint4 pu; pu.x = u[0]; pu.y = u[1]; pu.z = u[2]; pu.w = u[3];
            *(uint4*)&p_s[(ph * 16 + pr) * 36 + pcq] = pu;
        } else {
            float pm = fmaxf(E1pv * c2p1, E1nv * c2n1);
            float p  = ((bw >> pcq) & 1u) ? pm : 0.0f;
            unsigned uu = cvt_tf32(p);
            dsum += __uint_as_float(uu);
            p_s[pr * 36 + pcq] = __uint_as_float(uu);
        }
        // issue wh(t+1) into [(t+1)&1] (mma(t-1) done with it) + prefetch j-side
        if (t + 1 < NT) {
            const int j0n = (t + 1) * TJ;
            issue_wh((t + 1) & 1, j0n);
            if constexpr (NH == 4) {
                c2p4 = *(const float4*)&e2p[ph * NN + j0n + pcq];
                c2n4 = *(const float4*)&e2n[ph * NN + j0n + pcq];
            } else {
                c2p1 = e2p[j0n + pcq]; c2n1 = e2n[j0n + pcq];
            }
            bw = g_adjbits[(row0 + pr) * (NN / 32) + t + 1];
            cp_wait<1>();          // wh(t) arrived
        } else {
            cp_wait<0>();
        }
        __syncthreads();           // p_s + wh(t) visible to all
        // ---- mma phase ----
        const float* ws = wh_s[t & 1];
        const float* pa = &p_s[hw * 16 * 36];
#pragma unroll
        for (int ks = 0; ks < 4; ks++) {
            unsigned a0 = __float_as_uint(pa[g * 36 + 8 * ks + c]);
            unsigned a1 = __float_as_uint(pa[(g + 8) * 36 + 8 * ks + c]);
            unsigned a2 = __float_as_uint(pa[g * 36 + 8 * ks + c + 4]);
            unsigned a3 = __float_as_uint(pa[(g + 8) * 36 + 8 * ks + c + 4]);
#pragma unroll
            for (int q = 0; q < CHUNKS; q++) {
                int feat = warp * (8 * CHUNKS) + q * 8 + g;
                unsigned b0 = __float_as_uint(ws[(8 * ks + c) * WS + feat]);
                unsigned b1 = __float_as_uint(ws[(8 * ks + c + 4) * WS + feat]);
                mma_tf32(d[q], a0, a1, a2, a3, b0, b1);
            }
        }
    }

    // ---- denominator reduce + publish ----
    __syncthreads();
    if constexpr (NH == 4) {
        dsum += __shfl_xor_sync(0xffffffffu, dsum, 1);
        dsum += __shfl_xor_sync(0xffffffffu, dsum, 2);
        dsum += __shfl_xor_sync(0xffffffffu, dsum, 4);
        if ((tid & 7) == 0) denom_s[ph * 16 + pr] = dsum;
    } else {
#pragma unroll
        for (int off = 16; off; off >>= 1)
            dsum += __shfl_xor_sync(0xffffffffu, dsum, off);
        if (lane == 0) denom_s[pr] = dsum;
    }
    __syncthreads();

    // ---- normalize + ELU + store ----
    const float inv1 = 1.0f / denom_s[hw * 16 + g];
    const float inv2 = 1.0f / denom_s[hw * 16 + g + 8];
#pragma unroll
    for (int q = 0; q < CHUNKS; q++) {
        int feat = warp * (8 * CHUNKS) + q * 8 + 2 * c;
        float v0 = d[q][0] * inv1, v1 = d[q][1] * inv1;
        float v2 = d[q][2] * inv2, v3 = d[q][3] * inv2;
        v0 = v0 > 0.0f ? v0 : expm1f(v0);
        v1 = v1 > 0.0f ? v1 : expm1f(v1);
        v2 = v2 > 0.0f ? v2 : expm1f(v2);
        v3 = v3 > 0.0f ? v3 : expm1f(v3);
        *(float2*)&out[(row0 + g) * F + feat]     = make_float2(v0, v1);
        *(float2*)&out[(row0 + g + 8) * F + feat] = make_float2(v2, v3);
    }
}

__global__ void __launch_bounds__(512, 1) attn1_k() {
    attn_body<F1T, NH1>(g_Wh1, g_e1p_h, g_e1n_h, g_e2p_h, g_e2n_h, g_h1);
}
__global__ void __launch_bounds__(512, 1) attn2_k(float* __restrict__ out) {
    attn_body<F2T, 1>(g_Wh2, g_e1p_o, g_e1n_o, g_e2p_o, g_e2n_o, out);
}

// =======================================================================
extern "C" void kernel_launch(void* const* d_in, const int* in_sizes, int n_in,
                              void* d_out, int out_size) {
    const float* x       = (const float*)d_in[0];
    const int*   adj     = (const int*)  d_in[1];
    const float* W_heads = (const float*)d_in[2];
    const float* a_heads = (const float*)d_in[3];
    const float* W_out   = (const float*)d_in[4];
    const float* a_out   = (const float*)d_in[5];
    float* out = (float*)d_out;

    adjbits_k<<<NN, 128>>>(adj);
    gemm1_k<<<NN / 32, 512>>>(x, W_heads);
    fvec1_k<<<NN, 64>>>(a_heads);
    attn1_k<<<NN / 16, 512>>>();
    gemm2_k<<<NN / 32, 512>>>(W_out);
    fvec2_k<<<NN, 128>>>(a_out);
    attn2_k<<<NN / 16, 512>>>(out);
}